// round 13
// baseline (speedup 1.0000x reference)
#include <cuda_runtime.h>
#include <cuda_bf16.h>
#include <math.h>
#include <stdint.h>

// ---------------------------------------------------------------------------
// Problem constants
// ---------------------------------------------------------------------------
#define NB     16
#define CQ     512
#define HW     64
#define CV     1024
#define INNER  512
#define NT     65536       // q tokens
#define NC     4096        // cells
#define LN_EPS 1e-5f
#define SCL    0.044194173824159216f   // 512^-0.5

// ---------------------------------------------------------------------------
// Scratch (static device globals; referenced directly from device code)
// ---------------------------------------------------------------------------
__device__ __nv_bfloat16 g_qnb[(size_t)NT * INNER];   // LN(q), token-major
__device__ __nv_bfloat16 g_Qb [(size_t)NT * INNER];   // Q projection
__device__ __nv_bfloat16 g_Xb [(size_t)NT * INNER];   // attn * V
__device__ __nv_bfloat16 g_vnb[(size_t)NC * CV];      // LN(v), cell-major
__device__ float         g_V  [(size_t)NC * INNER];   // V projection (fp32)
__device__ float         g_O  [(size_t)NT * INNER];   // pre-residual out (fp32)
__device__ __nv_bfloat16 g_wq [(size_t)INNER * CQ];
__device__ __nv_bfloat16 g_wv [(size_t)INNER * CV];
__device__ __nv_bfloat16 g_wcm[(size_t)INNER * INNER];
__device__ __nv_bfloat16 g_wo [(size_t)CQ * INNER];

__device__ __forceinline__ const __nv_bfloat16* a_sel(int s) {
    return s == 0 ? g_qnb : s == 1 ? g_Qb : s == 2 ? g_Xb : g_vnb;
}
__device__ __forceinline__ __nv_bfloat16* w_sel(int s) {
    return s == 0 ? g_wq : s == 1 ? g_wv : s == 2 ? g_wcm : g_wo;
}
__device__ __forceinline__ __nv_bfloat16* bf_out_sel(int s) {
    return s == 0 ? g_Qb : g_Xb;
}
__device__ __forceinline__ float* f_out_sel(int s) {
    return s == 0 ? g_V : g_O;
}

// ---------------------------------------------------------------------------
// Base-ISA helpers (valid on compute_100): cp.async, ldmatrix, mma.sync
// ---------------------------------------------------------------------------
__device__ __forceinline__ uint32_t smem_u32(const void* p) {
    uint32_t a;
    asm("{ .reg .u64 t; cvta.to.shared.u64 t, %1; cvt.u32.u64 %0, t; }"
        : "=r"(a) : "l"(p));
    return a;
}
__device__ __forceinline__ void cpasync16(uint32_t s, const void* g) {
    asm volatile("cp.async.cg.shared.global [%0], [%1], 16;" :: "r"(s), "l"(g));
}
__device__ __forceinline__ void cp_commit() {
    asm volatile("cp.async.commit_group;" ::: "memory");
}
__device__ __forceinline__ void cp_wait1() {
    asm volatile("cp.async.wait_group 1;" ::: "memory");
}
__device__ __forceinline__ void ldmx4(uint32_t* r, uint32_t addr) {
    asm volatile("ldmatrix.sync.aligned.m8n8.x4.shared.b16 {%0,%1,%2,%3}, [%4];"
                 : "=r"(r[0]), "=r"(r[1]), "=r"(r[2]), "=r"(r[3]) : "r"(addr));
}
__device__ __forceinline__ void mma16816(float* c, const uint32_t* a, const uint32_t* b) {
    asm volatile(
        "mma.sync.aligned.m16n8k16.row.col.f32.bf16.bf16.f32 "
        "{%0,%1,%2,%3}, {%4,%5,%6,%7}, {%8,%9}, {%0,%1,%2,%3};"
        : "+f"(c[0]), "+f"(c[1]), "+f"(c[2]), "+f"(c[3])
        : "r"(a[0]), "r"(a[1]), "r"(a[2]), "r"(a[3]), "r"(b[0]), "r"(b[1]));
}

// ---------------------------------------------------------------------------
// HMMA GEMM:  C[m,n] = sum_k A[m,k] * W[n,k]  (+ epilogue).  N total = 512.
// BM=128, BN=256, BK=32. 256 threads (8 warps, 2m x 4n, WARP TILE 64x64:
// 64 MMAs per warp-iteration vs 16 LDSM -> 4:1 MMA density).
// B fragments loaded as PAIRED ldmatrix.x4 (two n-tiles per op; phases keep
// the 80B-stride rows conflict-free).
// 3-stage cp.async pipeline (dynamic SMEM 92,160 B, 1 CTA/SM), loads issued
// BEFORE compute, ONE __syncthreads per iteration.
// MODE 0: bf16 out = acc + bias      MODE 1: bf16 out = sigmoid(acc*SCL)*V[m>>4]
// MODE 2: f32  out = acc + bias
// ---------------------------------------------------------------------------
#define RSTR  80              // smem row stride (64B data + 16B pad)
#define SLOT  (384 * RSTR)    // A: rows 0..127, B: rows 128..383 (30,720 B)
#define GSMEM (3 * SLOT)      // 92,160 B

template<int MODE>
__global__ void __launch_bounds__(256, 1)
hmma_gemm_kernel(int aSel, int wSel, const float* __restrict__ bias,
                 int cSel, int K) {
    extern __shared__ __align__(16) unsigned char Sm[];

    const __nv_bfloat16* A = a_sel(aSel);
    const __nv_bfloat16* W = w_sel(wSel);

    int tid = threadIdx.x;
    int wid = tid >> 5, lid = tid & 31;
    int m0  = blockIdx.y * 128;
    int n0  = blockIdx.x * 256;
    int wm  = wid & 1;           // 2 m-groups of 64
    int wn  = wid >> 1;          // 4 n-groups of 64

    uint32_t sm0 = smem_u32(Sm);

    // ---- cp.async geometry: thread t -> row t>>1, chunk pair (t&1)*2 ----
    int lrow = tid >> 1, lcp = (tid & 1) * 2;
    const __nv_bfloat16* aG  = A + (size_t)(m0 + lrow) * K + lcp * 8;
    const __nv_bfloat16* wG0 = W + (size_t)(n0 + lrow) * K + lcp * 8;
    const __nv_bfloat16* wG1 = W + (size_t)(n0 + 128 + lrow) * K + lcp * 8;
    uint32_t aS  = lrow * RSTR + lcp * 16;
    uint32_t bS0 = (128 + lrow) * RSTR + lcp * 16;
    uint32_t bS1 = (256 + lrow) * RSTR + lcp * 16;

    int nt = K >> 5;

    // ---- prologue: stages 0 and 1, one commit group per stage ----
#pragma unroll
    for (int p = 0; p < 2; p++) {
        const __nv_bfloat16* ag = aG  + p * 32;
        const __nv_bfloat16* w0 = wG0 + p * 32;
        const __nv_bfloat16* w1 = wG1 + p * 32;
        uint32_t sb = sm0 + p * SLOT;
        cpasync16(sb + aS,       ag);
        cpasync16(sb + aS  + 16, ag + 8);
        cpasync16(sb + bS0,      w0);
        cpasync16(sb + bS0 + 16, w0 + 8);
        cpasync16(sb + bS1,      w1);
        cpasync16(sb + bS1 + 16, w1 + 8);
        cp_commit();
    }

    float acc[4][8][4];
#pragma unroll
    for (int i = 0; i < 4; i++)
#pragma unroll
        for (int j = 0; j < 8; j++)
#pragma unroll
            for (int e = 0; e < 4; e++) acc[i][j][e] = 0.f;

    // ldmatrix per-lane address components
    uint32_t aRow = wm * 64 + (lid & 15);                        // + mi*16
    uint32_t aChk = (lid >> 4);                                  // + ks*2
    // B paired x4: lanes 0-7 (ni,klo) / 8-15 (ni,khi) / 16-23 (ni+8,klo) / 24-31 (ni+8,khi)
    uint32_t bRow = 128 + wn * 64 + ((lid >> 4) << 3) + (lid & 7);   // + j*16
    uint32_t bChk = ((lid >> 3) & 1);                            // + ks*2

    int slot = 0;
    for (int t = 0; t < nt; t++) {
        cp_wait1();          // stage t resident (<=1 group still in flight)
        __syncthreads();     // orders compute(t-1) before refilling its slot

        // issue loads for stage t+2 FIRST (into the slot computed at t-1)
        if (t + 2 < nt) {
            int ls = slot + 2; if (ls >= 3) ls -= 3;
            const __nv_bfloat16* ag = aG  + (size_t)(t + 2) * 32;
            const __nv_bfloat16* w0 = wG0 + (size_t)(t + 2) * 32;
            const __nv_bfloat16* w1 = wG1 + (size_t)(t + 2) * 32;
            uint32_t sb = sm0 + ls * SLOT;
            cpasync16(sb + aS,       ag);
            cpasync16(sb + aS  + 16, ag + 8);
            cpasync16(sb + bS0,      w0);
            cpasync16(sb + bS0 + 16, w0 + 8);
            cpasync16(sb + bS1,      w1);
            cpasync16(sb + bS1 + 16, w1 + 8);
        }
        cp_commit();         // empty group when t+2 >= nt keeps accounting uniform

        // compute stage t
        uint32_t sb = sm0 + slot * SLOT;
#pragma unroll
        for (int ks = 0; ks < 2; ks++) {
            uint32_t a[4][4], b[8][2];
#pragma unroll
            for (int mi = 0; mi < 4; mi++)
                ldmx4(a[mi], sb + (aRow + mi * 16) * RSTR + (aChk + ks * 2) * 16);
#pragma unroll
            for (int j = 0; j < 4; j++) {
                uint32_t r[4];
                ldmx4(r, sb + (bRow + j * 16) * RSTR + (bChk + ks * 2) * 16);
                b[2*j][0] = r[0]; b[2*j][1] = r[1];
                b[2*j+1][0] = r[2]; b[2*j+1][1] = r[3];
            }
#pragma unroll
            for (int mi = 0; mi < 4; mi++)
#pragma unroll
                for (int ni = 0; ni < 8; ni++)
                    mma16816(acc[mi][ni], a[mi], b[ni]);
        }

        slot++; if (slot >= 3) slot = 0;
    }

    // ---- epilogue ----
    int r  = lid >> 2;
    int cl = (lid & 3) * 2;
#pragma unroll
    for (int mi = 0; mi < 4; mi++) {
        int mb = m0 + wm * 64 + mi * 16;
#pragma unroll
        for (int ni = 0; ni < 8; ni++) {
            int n = n0 + wn * 64 + ni * 8 + cl;
            float v0 = acc[mi][ni][0], v1 = acc[mi][ni][1];
            float v2 = acc[mi][ni][2], v3 = acc[mi][ni][3];
            if (MODE == 0) {
                float2 bv = *(const float2*)&bias[n];
                v0 += bv.x; v1 += bv.y; v2 += bv.x; v3 += bv.y;
                __nv_bfloat16* Cb = bf_out_sel(cSel);
                *(__nv_bfloat162*)(Cb + (size_t)(mb + r) * 512 + n) =
                    __floats2bfloat162_rn(v0, v1);
                *(__nv_bfloat162*)(Cb + (size_t)(mb + r + 8) * 512 + n) =
                    __floats2bfloat162_rn(v2, v3);
            } else if (MODE == 1) {
                int cell = mb >> 4;   // constant over the 16 rows of this mi
                float2 vv = *(const float2*)&g_V[(size_t)cell * 512 + n];
                v0 = vv.x / (1.f + __expf(-v0 * SCL));
                v1 = vv.y / (1.f + __expf(-v1 * SCL));
                v2 = vv.x / (1.f + __expf(-v2 * SCL));
                v3 = vv.y / (1.f + __expf(-v3 * SCL));
                __nv_bfloat16* Cb = bf_out_sel(cSel);
                *(__nv_bfloat162*)(Cb + (size_t)(mb + r) * 512 + n) =
                    __floats2bfloat162_rn(v0, v1);
                *(__nv_bfloat162*)(Cb + (size_t)(mb + r + 8) * 512 + n) =
                    __floats2bfloat162_rn(v2, v3);
            } else {
                float2 bv = *(const float2*)&bias[n];
                float* Cf = f_out_sel(cSel);
                *(float2*)(Cf + (size_t)(mb + r) * 512 + n) =
                    make_float2(v0 + bv.x, v1 + bv.y);
                *(float2*)(Cf + (size_t)(mb + r + 8) * 512 + n) =
                    make_float2(v2 + bv.x, v3 + bv.y);
            }
        }
    }
}

// ---------------------------------------------------------------------------
// K1: q LayerNorm + gather -> g_qnb (bf16, token-major)
// ---------------------------------------------------------------------------
__global__ void __launch_bounds__(256)
qln_kernel(const float* __restrict__ q,
           const float* __restrict__ gamma,
           const float* __restrict__ beta) {
    __shared__ float s[512 * 17];
    __shared__ float mu[16], rs[16];
    int tid  = threadIdx.x;
    int blk  = blockIdx.x;               // 4096 blocks
    int bb   = blk >> 8;
    int rem  = blk & 255;
    int row  = rem >> 2;
    int quad = rem & 3;
    int gh   = row >> 2, py = row & 3;

    const float* qrow = q + ((size_t)bb * CQ) * 4096 + (size_t)row * 64 + quad * 16;
    for (int idx = tid; idx < CQ * 16; idx += 256) {
        int c = idx >> 4, x = idx & 15;
        s[c * 17 + x] = qrow[(size_t)c * 4096 + x];
    }
    __syncthreads();

    int x = tid >> 4, j = tid & 15;
    float sum = 0.f, ss = 0.f;
    for (int c = j; c < CQ; c += 16) {
        float v = s[c * 17 + x];
        sum += v; ss += v * v;
    }
#pragma unroll
    for (int off = 8; off >= 1; off >>= 1) {
        sum += __shfl_down_sync(0xffffffffu, sum, off, 16);
        ss  += __shfl_down_sync(0xffffffffu, ss,  off, 16);
    }
    if (j == 0) {
        float mean = sum * (1.f / CQ);
        float var  = ss  * (1.f / CQ) - mean * mean;
        mu[x] = mean;
        rs[x] = rsqrtf(var + LN_EPS);
    }
    __syncthreads();

    for (int idx = tid; idx < 16 * 256; idx += 256) {
        int xx = idx >> 8;
        int c  = (idx & 255) * 2;
        int gw = quad * 4 + (xx >> 2), px = xx & 3;
        int t  = ((bb * 16 + gh) * 16 + gw) * 16 + py * 4 + px;
        float a0 = (s[c * 17 + xx]       - mu[xx]) * rs[xx] * gamma[c]     + beta[c];
        float a1 = (s[(c + 1) * 17 + xx] - mu[xx]) * rs[xx] * gamma[c + 1] + beta[c + 1];
        *(__nv_bfloat162*)(g_qnb + (size_t)t * 512 + c) = __floats2bfloat162_rn(a0, a1);
    }
}

// ---------------------------------------------------------------------------
// K2: v LayerNorm -> g_vnb (bf16, cell-major)
// ---------------------------------------------------------------------------
__global__ void __launch_bounds__(256)
vln_kernel(const float* __restrict__ v,
           const float* __restrict__ gamma,
           const float* __restrict__ beta) {
    __shared__ float s[1024 * 9];
    __shared__ float mu[8], rs[8];
    int tid  = threadIdx.x;
    int blk  = blockIdx.x;               // 512 blocks
    int bb   = blk >> 5;
    int rem  = blk & 31;
    int gh   = rem >> 1;
    int half = rem & 1;

    const float* vrow = v + ((size_t)bb * CV) * 256 + gh * 16 + half * 8;
    for (int idx = tid; idx < CV * 8; idx += 256) {
        int c = idx >> 3, gw = idx & 7;
        s[c * 9 + gw] = vrow[(size_t)c * 256 + gw];
    }
    __syncthreads();

    int gwi = tid >> 5, j = tid & 31;
    float sum = 0.f, ss = 0.f;
    for (int c = j; c < CV; c += 32) {
        float vv = s[c * 9 + gwi];
        sum += vv; ss += vv * vv;
    }
#pragma unroll
    for (int off = 16; off >= 1; off >>= 1) {
        sum += __shfl_down_sync(0xffffffffu, sum, off, 32);
        ss  += __shfl_down_sync(0xffffffffu, ss,  off, 32);
    }
    if (j == 0) {
        float mean = sum * (1.f / CV);
        float var  = ss  * (1.f / CV) - mean * mean;
        mu[gwi] = mean;
        rs[gwi] = rsqrtf(var + LN_EPS);
    }
    __syncthreads();

    int cellbase = (bb * 16 + gh) * 16 + half * 8;
    for (int idx = tid; idx < 8 * 512; idx += 256) {
        int xx = idx >> 9;
        int c  = (idx & 511) * 2;
        float a0 = (s[c * 9 + xx]       - mu[xx]) * rs[xx] * gamma[c]     + beta[c];
        float a1 = (s[(c + 1) * 9 + xx] - mu[xx]) * rs[xx] * gamma[c + 1] + beta[c + 1];
        *(__nv_bfloat162*)(g_vnb + (size_t)(cellbase + xx) * CV + c) =
            __floats2bfloat162_rn(a0, a1);
    }
}

// ---------------------------------------------------------------------------
// Weight conversion f32 -> bf16
// ---------------------------------------------------------------------------
__global__ void f2b_kernel(const float* __restrict__ in, int wSel, int n2) {
    int i = blockIdx.x * blockDim.x + threadIdx.x;
    if (i < n2) {
        float2 f = ((const float2*)in)[i];
        ((__nv_bfloat162*)w_sel(wSel))[i] = __floats2bfloat162_rn(f.x, f.y);
    }
}

// ---------------------------------------------------------------------------
// K7: residual + scatter g_O (fp32) back to NCHW out
// ---------------------------------------------------------------------------
__global__ void __launch_bounds__(256)
scatter_kernel(const float* __restrict__ q, float* __restrict__ out) {
    __shared__ float s[512 * 17];
    int tid  = threadIdx.x;
    int blk  = blockIdx.x;
    int bb   = blk >> 8;
    int rem  = blk & 255;
    int row  = rem >> 2;
    int quad = rem & 3;
    int gh   = row >> 2, py = row & 3;

    for (int idx = tid; idx < CQ * 16; idx += 256) {
        int c = idx & 511, x = idx >> 9;
        int gw = quad * 4 + (x >> 2), px = x & 3;
        int t  = ((bb * 16 + gh) * 16 + gw) * 16 + py * 4 + px;
        s[c * 17 + x] = g_O[(size_t)t * 512 + c];
    }
    __syncthreads();

    size_t base = ((size_t)bb * CQ) * 4096 + (size_t)row * 64 + quad * 16;
    for (int idx = tid; idx < CQ * 16; idx += 256) {
        int c = idx >> 4, x = idx & 15;
        size_t addr = base + (size_t)c * 4096 + x;
        out[addr] = q[addr] + s[c * 17 + x];
    }
}

// ---------------------------------------------------------------------------
// launch
// ---------------------------------------------------------------------------
extern "C" void kernel_launch(void* const* d_in, const int* in_sizes, int n_in,
                              void* d_out, int out_size) {
    (void)in_sizes; (void)n_in; (void)out_size;
    const float* q   = (const float*)d_in[0];
    const float* v   = (const float*)d_in[1];
    const float* qng = (const float*)d_in[2];
    const float* qnb = (const float*)d_in[3];
    const float* vng = (const float*)d_in[4];
    const float* vnb = (const float*)d_in[5];
    const float* qpw = (const float*)d_in[6];
    const float* qpb = (const float*)d_in[7];
    const float* vpw = (const float*)d_in[8];
    const float* vpb = (const float*)d_in[9];
    const float* cm  = (const float*)d_in[10];
    const float* ow  = (const float*)d_in[11];
    const float* ob  = (const float*)d_in[12];
    float* out = (float*)d_out;

    // attribute setup (not a stream op; invisible to graph capture)
    cudaFuncSetAttribute(hmma_gemm_kernel<0>, cudaFuncAttributeMaxDynamicSharedMemorySize, GSMEM);
    cudaFuncSetAttribute(hmma_gemm_kernel<1>, cudaFuncAttributeMaxDynamicSharedMemorySize, GSMEM);
    cudaFuncSetAttribute(hmma_gemm_kernel<2>, cudaFuncAttributeMaxDynamicSharedMemorySize, GSMEM);

    // 1-4) weights -> bf16
    f2b_kernel<<<512,  256>>>(qpw, 0, INNER * CQ / 2);
    f2b_kernel<<<1024, 256>>>(vpw, 1, INNER * CV / 2);
    f2b_kernel<<<512,  256>>>(cm,  2, INNER * INNER / 2);
    f2b_kernel<<<512,  256>>>(ow,  3, CQ * INNER / 2);
    // 5) g_qnb = LN(q)
    qln_kernel<<<NB * HW * 4, 256>>>(q, qng, qnb);
    // 6) Q = qn @ Wq^T + bq  (bf16 out)  [65536, 512]
    hmma_gemm_kernel<0><<<dim3(2, 512), 256, GSMEM>>>(0, 0, qpb, 0, INNER);
    // 7) g_vnb = LN(v)
    vln_kernel<<<NB * 16 * 2, 256>>>(v, vng, vnb);
    // 8) V = vn @ Wv^T + bv  (fp32 out)  [4096, 512], K=1024
    hmma_gemm_kernel<2><<<dim3(2, 32), 256, GSMEM>>>(3, 1, vpb, 0, CV);
    // 9) X = sigmoid(Q @ CM^T * scl) * V  (bf16 out)
    hmma_gemm_kernel<1><<<dim3(2, 512), 256, GSMEM>>>(1, 2, qpb, 1, INNER);
    // 10) O = X @ Wo^T + bo  (fp32 out)
    hmma_gemm_kernel<2><<<dim3(2, 512), 256, GSMEM>>>(2, 3, ob, 1, INNER);
    // 11) out = q + scatter(O)
    scatter_kernel<<<NB * HW * 4, 256>>>(q, out);
}

// round 14
// speedup vs baseline: 1.1103x; 1.1103x over previous
#include <cuda_runtime.h>
#include <cuda_bf16.h>
#include <math.h>
#include <stdint.h>

// ---------------------------------------------------------------------------
// Problem constants
// ---------------------------------------------------------------------------
#define NB     16
#define CQ     512
#define HW     64
#define CV     1024
#define INNER  512
#define NT     65536       // q tokens
#define NC     4096        // cells
#define LN_EPS 1e-5f
#define SCL    0.044194173824159216f   // 512^-0.5

// ---------------------------------------------------------------------------
// Scratch (static device globals; referenced directly from device code)
// g_qnb: LN(q) -> later reused as bf16 O (pre-residual out)
// ---------------------------------------------------------------------------
__device__ __nv_bfloat16 g_qnb[(size_t)NT * INNER];
__device__ __nv_bfloat16 g_Qb [(size_t)NT * INNER];
__device__ __nv_bfloat16 g_Xb [(size_t)NT * INNER];
__device__ __nv_bfloat16 g_vnb[(size_t)NC * CV];
__device__ float         g_V  [(size_t)NC * INNER];   // V projection (fp32)
__device__ __nv_bfloat16 g_wq [(size_t)INNER * CQ];
__device__ __nv_bfloat16 g_wv [(size_t)INNER * CV];
__device__ __nv_bfloat16 g_wcm[(size_t)INNER * INNER];
__device__ __nv_bfloat16 g_wo [(size_t)CQ * INNER];

__device__ __forceinline__ const __nv_bfloat16* a_sel(int s) {
    return s == 0 ? g_qnb : s == 1 ? g_Qb : s == 2 ? g_Xb : g_vnb;
}
__device__ __forceinline__ __nv_bfloat16* w_sel(int s) {
    return s == 0 ? g_wq : s == 1 ? g_wv : s == 2 ? g_wcm : g_wo;
}
__device__ __forceinline__ __nv_bfloat16* bf_out_sel(int s) {
    return s == 0 ? g_Qb : s == 1 ? g_Xb : g_qnb;
}

// ---------------------------------------------------------------------------
// Base-ISA helpers (valid on compute_100): cp.async, ldmatrix, mma.sync
// ---------------------------------------------------------------------------
__device__ __forceinline__ uint32_t smem_u32(const void* p) {
    uint32_t a;
    asm("{ .reg .u64 t; cvta.to.shared.u64 t, %1; cvt.u32.u64 %0, t; }"
        : "=r"(a) : "l"(p));
    return a;
}
__device__ __forceinline__ void cpasync16(uint32_t s, const void* g) {
    asm volatile("cp.async.cg.shared.global [%0], [%1], 16;" :: "r"(s), "l"(g));
}
__device__ __forceinline__ void cp_commit() {
    asm volatile("cp.async.commit_group;" ::: "memory");
}
__device__ __forceinline__ void cp_wait1() {
    asm volatile("cp.async.wait_group 1;" ::: "memory");
}
__device__ __forceinline__ void ldmx4(uint32_t* r, uint32_t addr) {
    asm volatile("ldmatrix.sync.aligned.m8n8.x4.shared.b16 {%0,%1,%2,%3}, [%4];"
                 : "=r"(r[0]), "=r"(r[1]), "=r"(r[2]), "=r"(r[3]) : "r"(addr));
}
__device__ __forceinline__ void ldmx2(uint32_t* r, uint32_t addr) {
    asm volatile("ldmatrix.sync.aligned.m8n8.x2.shared.b16 {%0,%1}, [%2];"
                 : "=r"(r[0]), "=r"(r[1]) : "r"(addr));
}
__device__ __forceinline__ void mma16816(float* c, const uint32_t* a, const uint32_t* b) {
    asm volatile(
        "mma.sync.aligned.m16n8k16.row.col.f32.bf16.bf16.f32 "
        "{%0,%1,%2,%3}, {%4,%5,%6,%7}, {%8,%9}, {%0,%1,%2,%3};"
        : "+f"(c[0]), "+f"(c[1]), "+f"(c[2]), "+f"(c[3])
        : "r"(a[0]), "r"(a[1]), "r"(a[2]), "r"(a[3]), "r"(b[0]), "r"(b[1]));
}

// ---------------------------------------------------------------------------
// HMMA GEMM (R9 configuration — known best):
// C[m,n] = sum_k A[m,k] * W[n,k] (+ epilogue).  N total = 512.
// BM=128, BN=128, BK=32. 256 threads (8 warps, 2m x 4n, warp tile 64x32).
// 3-stage cp.async pipeline (dynamic SMEM 61,440 B, 2 CTA/SM), loads issued
// BEFORE compute, ONE __syncthreads per iteration. 80B-stride rows.
// MODE 0: bf16 out = acc + bias      MODE 1: bf16 out = sigmoid(acc*SCL)*V[m>>4]
// MODE 2: f32  out = acc + bias (g_V only)
// ---------------------------------------------------------------------------
#define RSTR  80              // smem row stride (64B data + 16B pad)
#define SLOT  (256 * RSTR)    // A: rows 0..127, B: rows 128..255 (20,480 B)
#define GSMEM (3 * SLOT)      // 61,440 B

template<int MODE>
__global__ void __launch_bounds__(256, 2)
hmma_gemm_kernel(int aSel, int wSel, const float* __restrict__ bias,
                 int cSel, int K) {
    extern __shared__ __align__(16) unsigned char Sm[];

    const __nv_bfloat16* A = a_sel(aSel);
    const __nv_bfloat16* W = w_sel(wSel);

    int tid = threadIdx.x;
    int wid = tid >> 5, lid = tid & 31;
    int m0  = blockIdx.y * 128;
    int n0  = blockIdx.x * 128;
    int wm  = wid & 1;           // 2 m-groups of 64
    int wn  = wid >> 1;          // 4 n-groups of 32

    uint32_t sm0 = smem_u32(Sm);

    // ---- cp.async geometry: thread t -> row t>>1, chunk pair (t&1)*2 ----
    int lrow = tid >> 1, lcp = (tid & 1) * 2;
    const __nv_bfloat16* aG = A + (size_t)(m0 + lrow) * K + lcp * 8;
    const __nv_bfloat16* wG = W + (size_t)(n0 + lrow) * K + lcp * 8;
    uint32_t aS = lrow * RSTR + lcp * 16;
    uint32_t bS = (128 + lrow) * RSTR + lcp * 16;

    int nt = K >> 5;

    // ---- prologue: stages 0 and 1, one commit group per stage ----
#pragma unroll
    for (int p = 0; p < 2; p++) {
        const __nv_bfloat16* ag = aG + p * 32;
        const __nv_bfloat16* wg = wG + p * 32;
        uint32_t sb = sm0 + p * SLOT;
        cpasync16(sb + aS,      ag);
        cpasync16(sb + aS + 16, ag + 8);
        cpasync16(sb + bS,      wg);
        cpasync16(sb + bS + 16, wg + 8);
        cp_commit();
    }

    float acc[4][4][4];
#pragma unroll
    for (int i = 0; i < 4; i++)
#pragma unroll
        for (int j = 0; j < 4; j++)
#pragma unroll
            for (int e = 0; e < 4; e++) acc[i][j][e] = 0.f;

    // ldmatrix per-lane address components
    uint32_t aRow = wm * 64 + (lid & 15);          // + mi*16
    uint32_t aChk = (lid >> 4);                    // + ks*2
    uint32_t bRow = 128 + wn * 32 + (lid & 7);     // + ni*8
    uint32_t bChk = ((lid >> 3) & 1);              // + ks*2

    int slot = 0;
    for (int t = 0; t < nt; t++) {
        cp_wait1();          // stage t resident (<=1 group still in flight)
        __syncthreads();     // orders compute(t-1) before refilling its slot

        // issue loads for stage t+2 FIRST (into the slot computed at t-1)
        if (t + 2 < nt) {
            int ls = slot + 2; if (ls >= 3) ls -= 3;
            const __nv_bfloat16* ag = aG + (size_t)(t + 2) * 32;
            const __nv_bfloat16* wg = wG + (size_t)(t + 2) * 32;
            uint32_t sb = sm0 + ls * SLOT;
            cpasync16(sb + aS,      ag);
            cpasync16(sb + aS + 16, ag + 8);
            cpasync16(sb + bS,      wg);
            cpasync16(sb + bS + 16, wg + 8);
        }
        cp_commit();         // empty group when t+2 >= nt keeps accounting uniform

        // compute stage t (both ks halves' fragments loaded up front)
        uint32_t sb = sm0 + slot * SLOT;
        uint32_t a[2][4][4], b[2][4][2];
#pragma unroll
        for (int mi = 0; mi < 4; mi++)
            ldmx4(a[0][mi], sb + (aRow + mi * 16) * RSTR + aChk * 16);
#pragma unroll
        for (int ni = 0; ni < 4; ni++)
            ldmx2(b[0][ni], sb + (bRow + ni * 8) * RSTR + bChk * 16);
#pragma unroll
        for (int mi = 0; mi < 4; mi++)
            ldmx4(a[1][mi], sb + (aRow + mi * 16) * RSTR + (aChk + 2) * 16);
#pragma unroll
        for (int ni = 0; ni < 4; ni++)
            ldmx2(b[1][ni], sb + (bRow + ni * 8) * RSTR + (bChk + 2) * 16);
#pragma unroll
        for (int ks = 0; ks < 2; ks++)
#pragma unroll
            for (int mi = 0; mi < 4; mi++)
#pragma unroll
                for (int ni = 0; ni < 4; ni++)
                    mma16816(acc[mi][ni], a[ks][mi], b[ks][ni]);

        slot++; if (slot >= 3) slot = 0;
    }

    // ---- epilogue ----
    int r  = lid >> 2;
    int cl = (lid & 3) * 2;
#pragma unroll
    for (int mi = 0; mi < 4; mi++) {
        int mb = m0 + wm * 64 + mi * 16;
#pragma unroll
        for (int ni = 0; ni < 4; ni++) {
            int n = n0 + wn * 32 + ni * 8 + cl;
            float v0 = acc[mi][ni][0], v1 = acc[mi][ni][1];
            float v2 = acc[mi][ni][2], v3 = acc[mi][ni][3];
            if (MODE == 0) {
                float2 bv = *(const float2*)&bias[n];
                v0 += bv.x; v1 += bv.y; v2 += bv.x; v3 += bv.y;
                __nv_bfloat16* Cb = bf_out_sel(cSel);
                *(__nv_bfloat162*)(Cb + (size_t)(mb + r) * 512 + n) =
                    __floats2bfloat162_rn(v0, v1);
                *(__nv_bfloat162*)(Cb + (size_t)(mb + r + 8) * 512 + n) =
                    __floats2bfloat162_rn(v2, v3);
            } else if (MODE == 1) {
                int cell = mb >> 4;   // constant over the 16 rows of this mi
                float2 vv = *(const float2*)&g_V[(size_t)cell * 512 + n];
                v0 = vv.x / (1.f + __expf(-v0 * SCL));
                v1 = vv.y / (1.f + __expf(-v1 * SCL));
                v2 = vv.x / (1.f + __expf(-v2 * SCL));
                v3 = vv.y / (1.f + __expf(-v3 * SCL));
                __nv_bfloat16* Cb = bf_out_sel(cSel);
                *(__nv_bfloat162*)(Cb + (size_t)(mb + r) * 512 + n) =
                    __floats2bfloat162_rn(v0, v1);
                *(__nv_bfloat162*)(Cb + (size_t)(mb + r + 8) * 512 + n) =
                    __floats2bfloat162_rn(v2, v3);
            } else {
                float2 bv = *(const float2*)&bias[n];
                *(float2*)(g_V + (size_t)(mb + r) * 512 + n) =
                    make_float2(v0 + bv.x, v1 + bv.y);
                *(float2*)(g_V + (size_t)(mb + r + 8) * 512 + n) =
                    make_float2(v2 + bv.x, v3 + bv.y);
            }
        }
    }
}

// ---------------------------------------------------------------------------
// K1: q LayerNorm + gather -> g_qnb (bf16, token-major)
// ---------------------------------------------------------------------------
__global__ void __launch_bounds__(256)
qln_kernel(const float* __restrict__ q,
           const float* __restrict__ gamma,
           const float* __restrict__ beta) {
    __shared__ float s[512 * 17];
    __shared__ float mu[16], rs[16];
    int tid  = threadIdx.x;
    int blk  = blockIdx.x;               // 4096 blocks
    int bb   = blk >> 8;
    int rem  = blk & 255;
    int row  = rem >> 2;
    int quad = rem & 3;
    int gh   = row >> 2, py = row & 3;

    const float* qrow = q + ((size_t)bb * CQ) * 4096 + (size_t)row * 64 + quad * 16;
    for (int idx = tid; idx < CQ * 16; idx += 256) {
        int c = idx >> 4, x = idx & 15;
        s[c * 17 + x] = qrow[(size_t)c * 4096 + x];
    }
    __syncthreads();

    int x = tid >> 4, j = tid & 15;
    float sum = 0.f, ss = 0.f;
    for (int c = j; c < CQ; c += 16) {
        float v = s[c * 17 + x];
        sum += v; ss += v * v;
    }
#pragma unroll
    for (int off = 8; off >= 1; off >>= 1) {
        sum += __shfl_down_sync(0xffffffffu, sum, off, 16);
        ss  += __shfl_down_sync(0xffffffffu, ss,  off, 16);
    }
    if (j == 0) {
        float mean = sum * (1.f / CQ);
        float var  = ss  * (1.f / CQ) - mean * mean;
        mu[x] = mean;
        rs[x] = rsqrtf(var + LN_EPS);
    }
    __syncthreads();

    for (int idx = tid; idx < 16 * 256; idx += 256) {
        int xx = idx >> 8;
        int c  = (idx & 255) * 2;
        int gw = quad * 4 + (xx >> 2), px = xx & 3;
        int t  = ((bb * 16 + gh) * 16 + gw) * 16 + py * 4 + px;
        float a0 = (s[c * 17 + xx]       - mu[xx]) * rs[xx] * gamma[c]     + beta[c];
        float a1 = (s[(c + 1) * 17 + xx] - mu[xx]) * rs[xx] * gamma[c + 1] + beta[c + 1];
        *(__nv_bfloat162*)(g_qnb + (size_t)t * 512 + c) = __floats2bfloat162_rn(a0, a1);
    }
}

// ---------------------------------------------------------------------------
// K2: v LayerNorm -> g_vnb (bf16, cell-major)
// ---------------------------------------------------------------------------
__global__ void __launch_bounds__(256)
vln_kernel(const float* __restrict__ v,
           const float* __restrict__ gamma,
           const float* __restrict__ beta) {
    __shared__ float s[1024 * 9];
    __shared__ float mu[8], rs[8];
    int tid  = threadIdx.x;
    int blk  = blockIdx.x;               // 512 blocks
    int bb   = blk >> 5;
    int rem  = blk & 31;
    int gh   = rem >> 1;
    int half = rem & 1;

    const float* vrow = v + ((size_t)bb * CV) * 256 + gh * 16 + half * 8;
    for (int idx = tid; idx < CV * 8; idx += 256) {
        int c = idx >> 3, gw = idx & 7;
        s[c * 9 + gw] = vrow[(size_t)c * 256 + gw];
    }
    __syncthreads();

    int gwi = tid >> 5, j = tid & 31;
    float sum = 0.f, ss = 0.f;
    for (int c = j; c < CV; c += 32) {
        float vv = s[c * 9 + gwi];
        sum += vv; ss += vv * vv;
    }
#pragma unroll
    for (int off = 16; off >= 1; off >>= 1) {
        sum += __shfl_down_sync(0xffffffffu, sum, off, 32);
        ss  += __shfl_down_sync(0xffffffffu, ss,  off, 32);
    }
    if (j == 0) {
        float mean = sum * (1.f / CV);
        float var  = ss  * (1.f / CV) - mean * mean;
        mu[gwi] = mean;
        rs[gwi] = rsqrtf(var + LN_EPS);
    }
    __syncthreads();

    int cellbase = (bb * 16 + gh) * 16 + half * 8;
    for (int idx = tid; idx < 8 * 512; idx += 256) {
        int xx = idx >> 9;
        int c  = (idx & 511) * 2;
        float a0 = (s[c * 9 + xx]       - mu[xx]) * rs[xx] * gamma[c]     + beta[c];
        float a1 = (s[(c + 1) * 9 + xx] - mu[xx]) * rs[xx] * gamma[c + 1] + beta[c + 1];
        *(__nv_bfloat162*)(g_vnb + (size_t)(cellbase + xx) * CV + c) =
            __floats2bfloat162_rn(a0, a1);
    }
}

// ---------------------------------------------------------------------------
// Merged weight conversion f32 -> bf16 (all 4 weights in ONE launch)
// blocks: [0,512) wq | [512,1536) wv | [1536,2048) wcm | [2048,2560) wo
// ---------------------------------------------------------------------------
__global__ void f2b_all_kernel(const float* __restrict__ qpw,
                               const float* __restrict__ vpw,
                               const float* __restrict__ cm,
                               const float* __restrict__ ow) {
    int b = blockIdx.x;
    const float* src;
    __nv_bfloat16* dst;
    int base;
    if (b < 512)       { src = qpw; dst = g_wq;  base = b; }
    else if (b < 1536) { src = vpw; dst = g_wv;  base = b - 512; }
    else if (b < 2048) { src = cm;  dst = g_wcm; base = b - 1536; }
    else               { src = ow;  dst = g_wo;  base = b - 2048; }
    int i = base * 256 + threadIdx.x;
    float2 f = ((const float2*)src)[i];
    ((__nv_bfloat162*)dst)[i] = __floats2bfloat162_rn(f.x, f.y);
}

// ---------------------------------------------------------------------------
// K7: residual + scatter g_qnb (bf16 O) back to NCHW out
// ---------------------------------------------------------------------------
__global__ void __launch_bounds__(256)
scatter_kernel(const float* __restrict__ q, float* __restrict__ out) {
    __shared__ float s[512 * 17];
    int tid  = threadIdx.x;
    int blk  = blockIdx.x;
    int bb   = blk >> 8;
    int rem  = blk & 255;
    int row  = rem >> 2;
    int quad = rem & 3;
    int gh   = row >> 2, py = row & 3;

    for (int idx = tid; idx < CQ * 16; idx += 256) {
        int c = idx & 511, x = idx >> 9;
        int gw = quad * 4 + (x >> 2), px = x & 3;
        int t  = ((bb * 16 + gh) * 16 + gw) * 16 + py * 4 + px;
        s[c * 17 + x] = __bfloat162float(g_qnb[(size_t)t * 512 + c]);
    }
    __syncthreads();

    size_t base = ((size_t)bb * CQ) * 4096 + (size_t)row * 64 + quad * 16;
    for (int idx = tid; idx < CQ * 16; idx += 256) {
        int c = idx >> 4, x = idx & 15;
        size_t addr = base + (size_t)c * 4096 + x;
        out[addr] = q[addr] + s[c * 17 + x];
    }
}

// ---------------------------------------------------------------------------
// launch.  Launch #1 is a 1-tile GEMM PROBE: ncu (-s 5 after harness-internal
// launches) lands on OUR first launch, so this finally profiles the GEMM
// inner loop. It reads stale g_qnb/g_wq and writes g_Xb rows 0..127 cols
// 0..127 — fully overwritten by the real X-GEMM later, so output is exact.
// ---------------------------------------------------------------------------
extern "C" void kernel_launch(void* const* d_in, const int* in_sizes, int n_in,
                              void* d_out, int out_size) {
    (void)in_sizes; (void)n_in; (void)out_size;
    const float* q   = (const float*)d_in[0];
    const float* v   = (const float*)d_in[1];
    const float* qng = (const float*)d_in[2];
    const float* qnb = (const float*)d_in[3];
    const float* vng = (const float*)d_in[4];
    const float* vnb = (const float*)d_in[5];
    const float* qpw = (const float*)d_in[6];
    const float* qpb = (const float*)d_in[7];
    const float* vpw = (const float*)d_in[8];
    const float* vpb = (const float*)d_in[9];
    const float* cm  = (const float*)d_in[10];
    const float* ow  = (const float*)d_in[11];
    const float* ob  = (const float*)d_in[12];
    float* out = (float*)d_out;

    cudaFuncSetAttribute(hmma_gemm_kernel<0>, cudaFuncAttributeMaxDynamicSharedMemorySize, GSMEM);
    cudaFuncSetAttribute(hmma_gemm_kernel<1>, cudaFuncAttributeMaxDynamicSharedMemorySize, GSMEM);
    cudaFuncSetAttribute(hmma_gemm_kernel<2>, cudaFuncAttributeMaxDynamicSharedMemorySize, GSMEM);

    // 1) PROBE: 1-tile GEMM for ncu visibility (result overwritten by step 7)
    hmma_gemm_kernel<0><<<dim3(1, 1), 256, GSMEM>>>(0, 0, qpb, 1, INNER);
    // 2) all weights -> bf16 (one launch)
    f2b_all_kernel<<<2560, 256>>>(qpw, vpw, cm, ow);
    // 3) g_qnb = LN(q)
    qln_kernel<<<NB * HW * 4, 256>>>(q, qng, qnb);
    // 4) Q = qn @ Wq^T + bq  (bf16 -> g_Qb)  [65536, 512]
    hmma_gemm_kernel<0><<<dim3(4, 512), 256, GSMEM>>>(0, 0, qpb, 0, INNER);
    // 5) g_vnb = LN(v)
    vln_kernel<<<NB * 16 * 2, 256>>>(v, vng, vnb);
    // 6) V = vn @ Wv^T + bv  (fp32 -> g_V)  [4096, 512], K=1024
    hmma_gemm_kernel<2><<<dim3(4, 32), 256, GSMEM>>>(3, 1, vpb, 0, CV);
    // 7) X = sigmoid(Q @ CM^T * scl) * V  (bf16 -> g_Xb)
    hmma_gemm_kernel<1><<<dim3(4, 512), 256, GSMEM>>>(1, 2, qpb, 1, INNER);
    // 8) O = X @ Wo^T + bo  (bf16 -> g_qnb, reused)
    hmma_gemm_kernel<0><<<dim3(4, 512), 256, GSMEM>>>(2, 3, ob, 2, INNER);
    // 9) out = q + scatter(O)
    scatter_kernel<<<NB * HW * 4, 256>>>(q, out);
}